// round 3
// baseline (speedup 1.0000x reference)
#include <cuda_runtime.h>
#include <mma.h>
#include <math.h>

using namespace nvcuda;

// Problem constants
#define BATCH 2
#define C 512
#define NTOK 4096            // 16*16*16
#define GROUPS 32
#define CPG 16               // C / GROUPS
#define CN (C * NTOK)        // per-batch hn/q/k/v/o size
#define NN ((long)NTOK * NTOK)

// ---------------- scratch (device globals; no allocations allowed) ------------
__device__ float g_hn[(long)BATCH * CN];
__device__ float g_q [(long)BATCH * CN];
__device__ float g_k [(long)BATCH * CN];
__device__ float g_v [(long)BATCH * CN];
__device__ float g_o [(long)BATCH * CN];
__device__ float g_s [(long)BATCH * NN];   // attention scores / probs (128 MB)

// ---------------- GroupNorm ---------------------------------------------------
__global__ void __launch_bounds__(256) groupnorm_kernel(
    const float* __restrict__ x, const float* __restrict__ w,
    const float* __restrict__ b, float* __restrict__ hn)
{
    const int g  = blockIdx.x;
    const int bb = blockIdx.y;
    const long base = ((long)bb * C + (long)g * CPG) * NTOK;
    const int total = CPG * NTOK;

    float s = 0.f, s2 = 0.f;
    for (int i = threadIdx.x; i < total; i += 256) {
        float v = x[base + i];
        s += v; s2 += v * v;
    }
    __shared__ float rs[256], rs2[256];
    rs[threadIdx.x] = s; rs2[threadIdx.x] = s2;
    __syncthreads();
    for (int off = 128; off > 0; off >>= 1) {
        if (threadIdx.x < off) {
            rs[threadIdx.x]  += rs[threadIdx.x + off];
            rs2[threadIdx.x] += rs2[threadIdx.x + off];
        }
        __syncthreads();
    }
    const float mean = rs[0] / (float)total;
    const float var  = rs2[0] / (float)total - mean * mean;
    const float rstd = rsqrtf(var + 1e-6f);

    for (int i = threadIdx.x; i < total; i += 256) {
        int c = g * CPG + i / NTOK;
        hn[base + i] = (x[base + i] - mean) * rstd * w[c] + b[c];
    }
}

// ---------------- TF32 tensor-core batched GEMM -------------------------------
// C[m,n] = scale * sum_k A(m,k) * B(k,n) + bias[m] + R[m,n]
// AT: A stored A[k*lda + m]; BT: B stored B[n*ldb + k].
// Block tile 128x128x32, 8 warps (4 in m, 2 in n), warp tile 32x64,
// wmma 16x16x8 tf32 fragments (2x4 per warp).
#define BM 128
#define BN 128
#define BK 32
#define LDAS 40     // BK + 8 pad (row stride of As, in floats)
#define LDBS 136    // BN + 8 pad

template <bool AT, bool BT>
__global__ void __launch_bounds__(256) tf32_gemm_kernel(
    const float* __restrict__ A, const float* __restrict__ B,
    float* __restrict__ Cmat, int K, int lda, int ldb, int ldc,
    long sA, long sB, long sC,
    const float* __restrict__ bias, float scale,
    const float* __restrict__ R, long sR)
{
    const int bz = blockIdx.z;
    A += (long)bz * sA;
    B += (long)bz * sB;
    Cmat += (long)bz * sC;
    if (R) R += (long)bz * sR;

    const int m0 = blockIdx.y * BM;
    const int n0 = blockIdx.x * BN;

    __shared__ __align__(32) float As[BM * LDAS];   // m x k, 20.0 KB
    __shared__ __align__(32) float Bs[BK * LDBS];   // k x n, 17.0 KB
    __shared__ __align__(32) float Cst[8 * 256];    // per-warp 16x16 staging, 8 KB

    const int tid  = threadIdx.x;
    const int warp = tid >> 5;
    const int lane = tid & 31;
    const int wm = warp & 3;       // 0..3 (m)
    const int wn = warp >> 2;      // 0..1 (n)

    wmma::fragment<wmma::accumulator, 16, 16, 8, float> cf[2][4];
#pragma unroll
    for (int i = 0; i < 2; i++)
#pragma unroll
        for (int j = 0; j < 4; j++) wmma::fill_fragment(cf[i][j], 0.f);

    for (int k0 = 0; k0 < K; k0 += BK) {
        // ---- load A tile (128 x 32) ----
#pragma unroll
        for (int it = 0; it < 16; it++) {
            int t = tid + it * 256;
            if (AT) {
                int k = t >> 7, m = t & 127;
                As[m * LDAS + k] = A[(long)(k0 + k) * lda + (m0 + m)];
            } else {
                int m = t >> 5, k = t & 31;
                As[m * LDAS + k] = A[(long)(m0 + m) * lda + (k0 + k)];
            }
        }
        // ---- load B tile (32 x 128) ----
#pragma unroll
        for (int it = 0; it < 16; it++) {
            int t = tid + it * 256;
            if (BT) {
                int n = t >> 5, k = t & 31;
                Bs[k * LDBS + n] = B[(long)(n0 + n) * ldb + (k0 + k)];
            } else {
                int k = t >> 7, n = t & 127;
                Bs[k * LDBS + n] = B[(long)(k0 + k) * ldb + (n0 + n)];
            }
        }
        __syncthreads();

#pragma unroll
        for (int kk = 0; kk < BK; kk += 8) {
            wmma::fragment<wmma::matrix_a, 16, 16, 8, wmma::precision::tf32,
                           wmma::row_major> af[2];
            wmma::fragment<wmma::matrix_b, 16, 16, 8, wmma::precision::tf32,
                           wmma::row_major> bf[4];
#pragma unroll
            for (int i = 0; i < 2; i++) {
                wmma::load_matrix_sync(af[i],
                    &As[(wm * 32 + i * 16) * LDAS + kk], LDAS);
#pragma unroll
                for (int t = 0; t < af[i].num_elements; t++)
                    af[i].x[t] = wmma::__float_to_tf32(af[i].x[t]);
            }
#pragma unroll
            for (int j = 0; j < 4; j++) {
                wmma::load_matrix_sync(bf[j],
                    &Bs[kk * LDBS + wn * 64 + j * 16], LDBS);
#pragma unroll
                for (int t = 0; t < bf[j].num_elements; t++)
                    bf[j].x[t] = wmma::__float_to_tf32(bf[j].x[t]);
            }
#pragma unroll
            for (int i = 0; i < 2; i++)
#pragma unroll
                for (int j = 0; j < 4; j++)
                    wmma::mma_sync(cf[i][j], af[i], bf[j], cf[i][j]);
        }
        __syncthreads();
    }

    // ---- fused epilogue: scale, +bias[m], +R[m,n] ----
    float* stage = &Cst[warp * 256];
#pragma unroll
    for (int i = 0; i < 2; i++) {
#pragma unroll
        for (int j = 0; j < 4; j++) {
            wmma::store_matrix_sync(stage, cf[i][j], 16, wmma::mem_row_major);
            __syncwarp();
            const int mbase = m0 + wm * 32 + i * 16;
            const int nbase = n0 + wn * 64 + j * 16;
#pragma unroll
            for (int e = lane; e < 256; e += 32) {
                int r = e >> 4, cc = e & 15;
                int m = mbase + r, n = nbase + cc;
                float v = stage[e] * scale;
                if (bias) v += bias[m];
                if (R)    v += R[(long)m * ldc + n];
                Cmat[(long)m * ldc + n] = v;
            }
            __syncwarp();
        }
    }
}

// ---------------- row softmax over 4096 --------------------------------------
__global__ void __launch_bounds__(256) softmax_kernel(float* __restrict__ S)
{
    const long row = (long)blockIdx.y * gridDim.x + blockIdx.x;  // b*NTOK + i
    float* p = S + row * NTOK;
    const int tid = threadIdx.x;

    float vals[16];
    float mx = -1e30f;
#pragma unroll
    for (int i = 0; i < 4; i++) {
        float4 v4 = ((const float4*)p)[tid + i * 256];
        vals[i*4+0] = v4.x; vals[i*4+1] = v4.y;
        vals[i*4+2] = v4.z; vals[i*4+3] = v4.w;
        mx = fmaxf(fmaxf(fmaxf(mx, v4.x), fmaxf(v4.y, v4.z)), v4.w);
    }

    __shared__ float sm[32];
#pragma unroll
    for (int o = 16; o > 0; o >>= 1) mx = fmaxf(mx, __shfl_xor_sync(0xffffffffu, mx, o));
    if ((tid & 31) == 0) sm[tid >> 5] = mx;
    __syncthreads();
    if (tid < 32) {
        float v = (tid < 8) ? sm[tid] : -1e30f;
#pragma unroll
        for (int o = 4; o > 0; o >>= 1) v = fmaxf(v, __shfl_xor_sync(0xffffffffu, v, o));
        if (tid == 0) sm[0] = v;
    }
    __syncthreads();
    mx = sm[0];
    __syncthreads();

    float sum = 0.f;
#pragma unroll
    for (int i = 0; i < 16; i++) {
        vals[i] = expf(vals[i] - mx);
        sum += vals[i];
    }
#pragma unroll
    for (int o = 16; o > 0; o >>= 1) sum += __shfl_xor_sync(0xffffffffu, sum, o);
    if ((tid & 31) == 0) sm[tid >> 5] = sum;
    __syncthreads();
    if (tid < 32) {
        float v = (tid < 8) ? sm[tid] : 0.f;
#pragma unroll
        for (int o = 4; o > 0; o >>= 1) v += __shfl_xor_sync(0xffffffffu, v, o);
        if (tid == 0) sm[0] = v;
    }
    __syncthreads();
    const float inv = 1.f / sm[0];
#pragma unroll
    for (int i = 0; i < 4; i++) {
        float4 v4;
        v4.x = vals[i*4+0] * inv; v4.y = vals[i*4+1] * inv;
        v4.z = vals[i*4+2] * inv; v4.w = vals[i*4+3] * inv;
        ((float4*)p)[tid + i * 256] = v4;
    }
}

// ---------------- launcher ----------------------------------------------------
extern "C" void kernel_launch(void* const* d_in, const int* in_sizes, int n_in,
                              void* d_out, int out_size)
{
    const float* x    = (const float*)d_in[0];
    const float* gn_w = (const float*)d_in[1];
    const float* gn_b = (const float*)d_in[2];
    const float* wq   = (const float*)d_in[3];
    const float* bq   = (const float*)d_in[4];
    const float* wk   = (const float*)d_in[5];
    const float* bk   = (const float*)d_in[6];
    const float* wv   = (const float*)d_in[7];
    const float* bv   = (const float*)d_in[8];
    const float* wp   = (const float*)d_in[9];
    const float* bp   = (const float*)d_in[10];
    float* out = (float*)d_out;

    float *hn, *q, *k, *v, *o, *s;
    cudaGetSymbolAddress((void**)&hn, g_hn);
    cudaGetSymbolAddress((void**)&q,  g_q);
    cudaGetSymbolAddress((void**)&k,  g_k);
    cudaGetSymbolAddress((void**)&v,  g_v);
    cudaGetSymbolAddress((void**)&o,  g_o);
    cudaGetSymbolAddress((void**)&s,  g_s);

    // 1. GroupNorm
    groupnorm_kernel<<<dim3(GROUPS, BATCH), 256>>>(x, gn_w, gn_b, hn);

    // 2. Q/K/V projections: [512x512] @ [512x4096] per batch
    {
        dim3 grid(NTOK / BN, C / BM, BATCH);
        tf32_gemm_kernel<false, false><<<grid, 256>>>(wq, hn, q, C, C, NTOK, NTOK,
                                                      0, CN, CN, bq, 1.f, nullptr, 0);
        tf32_gemm_kernel<false, false><<<grid, 256>>>(wk, hn, k, C, C, NTOK, NTOK,
                                                      0, CN, CN, bk, 1.f, nullptr, 0);
        tf32_gemm_kernel<false, false><<<grid, 256>>>(wv, hn, v, C, C, NTOK, NTOK,
                                                      0, CN, CN, bv, 1.f, nullptr, 0);
    }

    // 3. scores[i,j] = (1/sqrt(C)) * sum_c q[c,i] k[c,j]   (A transposed)
    {
        dim3 grid(NTOK / BN, NTOK / BM, BATCH);
        const float scale = 0.044194173824159216f; // 512^-0.5
        tf32_gemm_kernel<true, false><<<grid, 256>>>(q, k, s, C, NTOK, NTOK, NTOK,
                                                     CN, CN, NN, nullptr, scale,
                                                     nullptr, 0);
    }

    // 4. softmax over j (rows of length 4096)
    softmax_kernel<<<dim3(NTOK, BATCH), 256>>>(s);

    // 5. o[c,i] = sum_j v[c,j] * attn[i,j]   (B transposed)
    {
        dim3 grid(NTOK / BN, C / BM, BATCH);
        tf32_gemm_kernel<false, true><<<grid, 256>>>(v, s, o, NTOK, NTOK, NTOK, NTOK,
                                                     CN, NN, CN, nullptr, 1.f,
                                                     nullptr, 0);
    }

    // 6. out = x + wp @ o + bp
    {
        dim3 grid(NTOK / BN, C / BM, BATCH);
        tf32_gemm_kernel<false, false><<<grid, 256>>>(wp, o, out, C, C, NTOK, NTOK,
                                                      0, CN, CN, bp, 1.f, x, CN);
    }
}

// round 5
// speedup vs baseline: 7.7217x; 7.7217x over previous
#include <cuda_runtime.h>
#include <cuda_fp16.h>
#include <mma.h>
#include <math.h>

using namespace nvcuda;

// Problem constants
#define BATCH 2
#define C 512
#define NTOK 4096
#define GROUPS 32
#define CPG 16
#define CN (C * NTOK)
#define NN ((long)NTOK * NTOK)

// ---------------- scratch (device globals) ------------------------------------
__device__ __half g_hn[(long)BATCH * CN];
__device__ __half g_q [(long)BATCH * CN];
__device__ __half g_k [(long)BATCH * CN];
__device__ __half g_v [(long)BATCH * CN];
__device__ __half g_o [(long)BATCH * CN];
__device__ float  g_s [(long)BATCH * NN];       // fp32 scores (134 MB)
__device__ __half g_p [(long)BATCH * NN];       // fp16 probs  (67 MB)
__device__ __half g_wh[4L * C * C];             // fp16 weights

// ---------------- weight conversion -------------------------------------------
__global__ void __launch_bounds__(256) convert_w_kernel(
    const float* __restrict__ wq, const float* __restrict__ wk,
    const float* __restrict__ wv, const float* __restrict__ wp,
    __half* __restrict__ wh)
{
    const int n = C * C;
    for (int i = blockIdx.x * 256 + threadIdx.x; i < n; i += gridDim.x * 256) {
        wh[i]           = __float2half_rn(wq[i]);
        wh[i + n]       = __float2half_rn(wk[i]);
        wh[i + 2 * n]   = __float2half_rn(wv[i]);
        wh[i + 3 * n]   = __float2half_rn(wp[i]);
    }
}

// ---------------- GroupNorm (fp32 in, fp16 out) --------------------------------
__global__ void __launch_bounds__(256) groupnorm_kernel(
    const float* __restrict__ x, const float* __restrict__ w,
    const float* __restrict__ b, __half* __restrict__ hn)
{
    const int g  = blockIdx.x;
    const int bb = blockIdx.y;
    const long base = ((long)bb * C + (long)g * CPG) * NTOK;
    const int total = CPG * NTOK;

    float s = 0.f, s2 = 0.f;
    for (int i = threadIdx.x; i < total / 4; i += 256) {
        float4 v = ((const float4*)(x + base))[i];
        s  += v.x + v.y + v.z + v.w;
        s2 += v.x*v.x + v.y*v.y + v.z*v.z + v.w*v.w;
    }
    __shared__ float rs[256], rs2[256];
    rs[threadIdx.x] = s; rs2[threadIdx.x] = s2;
    __syncthreads();
    for (int off = 128; off > 0; off >>= 1) {
        if (threadIdx.x < off) {
            rs[threadIdx.x]  += rs[threadIdx.x + off];
            rs2[threadIdx.x] += rs2[threadIdx.x + off];
        }
        __syncthreads();
    }
    const float mean = rs[0] / (float)total;
    const float var  = rs2[0] / (float)total - mean * mean;
    const float rstd = rsqrtf(var + 1e-6f);

    for (int i = threadIdx.x; i < total / 4; i += 256) {
        float4 v = ((const float4*)(x + base))[i];
        int c = g * CPG + (i * 4) / NTOK;   // 4 elems never straddle channels (NTOK%4==0)
        float sc = rstd * w[c], sh = b[c] - mean * sc;
        __half2 h0 = __floats2half2_rn(v.x * sc + sh, v.y * sc + sh);
        __half2 h1 = __floats2half2_rn(v.z * sc + sh, v.w * sc + sh);
        uint2 o; o.x = *(unsigned*)&h0; o.y = *(unsigned*)&h1;
        ((uint2*)(hn + base))[i] = o;
    }
}

// ---------------- fp16 tensor-core batched GEMM -------------------------------
// C[m,n] = scale * sum_k A(m,k)*B(k,n) + bias[m] + R[m,n]
// AT: A stored A[k*lda+m]; BT: B stored B[n*ldb+k]. K%32==0, M,N%128==0.
#define BM 128
#define BN 128
#define BKH 32

__device__ __forceinline__ void cp16(void* s, const void* g) {
    unsigned sa = (unsigned)__cvta_generic_to_shared(s);
    asm volatile("cp.async.cg.shared.global [%0], [%1], 16;\n" :: "r"(sa), "l"(g));
}
#define CP_COMMIT() asm volatile("cp.async.commit_group;\n" ::: "memory")
#define CP_WAIT1()  asm volatile("cp.async.wait_group 1;\n" ::: "memory")

template <bool AT, bool BT, typename OutT>
__global__ void __launch_bounds__(256) h_gemm_kernel(
    const __half* __restrict__ A, const __half* __restrict__ B,
    OutT* __restrict__ Cmat, int K, int lda, int ldb, int ldc,
    long sA, long sB, long sC,
    const float* __restrict__ bias, float scale,
    const float* __restrict__ R, long sR)
{
    const int bz = blockIdx.z;
    A += (long)bz * sA;
    B += (long)bz * sB;
    Cmat += (long)bz * sC;
    if (R) R += (long)bz * sR;

    const int m0 = blockIdx.y * BM;
    const int n0 = blockIdx.x * BN;

    // stage size 5120 halfs covers both layouts:
    //  row-major-ish [128][40] (pad 8) or k-major [32][136] (pad 8)
    __shared__ __align__(16) __half As[2][5120];
    __shared__ __align__(16) __half Bs[2][5120];

    const int tid  = threadIdx.x;
    const int warp = tid >> 5;
    const int lane = tid & 31;
    const int wm = warp & 1;      // 2 warps in m (64 rows each)
    const int wn = warp >> 1;     // 4 warps in n (32 cols each)

    wmma::fragment<wmma::accumulator, 16, 16, 16, float> cf[4][2];
#pragma unroll
    for (int i = 0; i < 4; i++)
#pragma unroll
        for (int j = 0; j < 2; j++) wmma::fill_fragment(cf[i][j], 0.f);

    auto loadA = [&](int st, int kt) {
        const int k0 = kt * BKH;
#pragma unroll
        for (int r = 0; r < 2; r++) {
            int t = tid + r * 256;
            if (AT) {           // A[k*lda + m], 16B contiguous in m
                int k = t >> 4, ch = t & 15;
                cp16(&As[st][k * 136 + ch * 8],
                     &A[(long)(k0 + k) * lda + m0 + ch * 8]);
            } else {            // A[m*lda + k], contiguous in k
                int m = t >> 2, ch = t & 3;
                cp16(&As[st][m * 40 + ch * 8],
                     &A[(long)(m0 + m) * lda + k0 + ch * 8]);
            }
        }
    };
    auto loadB = [&](int st, int kt) {
        const int k0 = kt * BKH;
#pragma unroll
        for (int r = 0; r < 2; r++) {
            int t = tid + r * 256;
            if (BT) {           // B[n*ldb + k], contiguous in k
                int n = t >> 2, ch = t & 3;
                cp16(&Bs[st][n * 40 + ch * 8],
                     &B[(long)(n0 + n) * ldb + k0 + ch * 8]);
            } else {            // B[k*ldb + n], contiguous in n
                int k = t >> 4, ch = t & 15;
                cp16(&Bs[st][k * 136 + ch * 8],
                     &B[(long)(k0 + k) * ldb + n0 + ch * 8]);
            }
        }
    };

    const int KT = K / BKH;
    loadA(0, 0); loadB(0, 0);
    CP_COMMIT();

    for (int kt = 0; kt < KT; kt++) {
        const int buf = kt & 1;
        if (kt + 1 < KT) { loadA(buf ^ 1, kt + 1); loadB(buf ^ 1, kt + 1); }
        CP_COMMIT();
        CP_WAIT1();
        __syncthreads();

#pragma unroll
        for (int kk = 0; kk < BKH; kk += 16) {
            typedef typename wmma::fragment<wmma::matrix_a, 16, 16, 16, __half,
                typename std::conditional<AT, wmma::col_major, wmma::row_major>::type> AFrag;
            typedef typename wmma::fragment<wmma::matrix_b, 16, 16, 16, __half,
                typename std::conditional<BT, wmma::col_major, wmma::row_major>::type> BFrag;
            AFrag af[4];
            BFrag bf[2];
#pragma unroll
            for (int i = 0; i < 4; i++) {
                if (AT)
                    wmma::load_matrix_sync(af[i], &As[buf][kk * 136 + wm * 64 + i * 16], 136);
                else
                    wmma::load_matrix_sync(af[i], &As[buf][(wm * 64 + i * 16) * 40 + kk], 40);
            }
#pragma unroll
            for (int j = 0; j < 2; j++) {
                if (BT)
                    wmma::load_matrix_sync(bf[j], &Bs[buf][(wn * 32 + j * 16) * 40 + kk], 40);
                else
                    wmma::load_matrix_sync(bf[j], &Bs[buf][kk * 136 + wn * 32 + j * 16], 136);
            }
#pragma unroll
            for (int i = 0; i < 4; i++)
#pragma unroll
                for (int j = 0; j < 2; j++)
                    wmma::mma_sync(cf[i][j], af[i], bf[j], cf[i][j]);
        }
        __syncthreads();
    }

    // ---- epilogue: scale, +bias[m], +R[m,n], convert ----
    float* cst = reinterpret_cast<float*>(As);       // reuse smem (>=8KB)
    float* stage = cst + warp * 256;
    const int r  = lane >> 1;        // 0..15 row within frag
    const int ch = lane & 1;         // 0/1: which 8-col chunk

#pragma unroll
    for (int i = 0; i < 4; i++) {
#pragma unroll
        for (int j = 0; j < 2; j++) {
            wmma::store_matrix_sync(stage, cf[i][j], 16, wmma::mem_row_major);
            __syncwarp();
            const int m = m0 + wm * 64 + i * 16 + r;
            const int n = n0 + wn * 32 + j * 16 + ch * 8;
            float4 v0 = ((float4*)stage)[r * 4 + ch * 2];
            float4 v1 = ((float4*)stage)[r * 4 + ch * 2 + 1];
            float bv = bias ? bias[m] : 0.f;
            v0.x = v0.x * scale + bv; v0.y = v0.y * scale + bv;
            v0.z = v0.z * scale + bv; v0.w = v0.w * scale + bv;
            v1.x = v1.x * scale + bv; v1.y = v1.y * scale + bv;
            v1.z = v1.z * scale + bv; v1.w = v1.w * scale + bv;
            if (R) {
                const float4* rp = (const float4*)(R + (long)m * ldc + n);
                float4 r0 = rp[0], r1 = rp[1];
                v0.x += r0.x; v0.y += r0.y; v0.z += r0.z; v0.w += r0.w;
                v1.x += r1.x; v1.y += r1.y; v1.z += r1.z; v1.w += r1.w;
            }
            if (sizeof(OutT) == 2) {
                __half2 h0 = __floats2half2_rn(v0.x, v0.y);
                __half2 h1 = __floats2half2_rn(v0.z, v0.w);
                __half2 h2 = __floats2half2_rn(v1.x, v1.y);
                __half2 h3 = __floats2half2_rn(v1.z, v1.w);
                uint4 o;
                o.x = *(unsigned*)&h0; o.y = *(unsigned*)&h1;
                o.z = *(unsigned*)&h2; o.w = *(unsigned*)&h3;
                *((uint4*)((__half*)Cmat + (long)m * ldc + n)) = o;
            } else {
                float4* cp = (float4*)((float*)Cmat + (long)m * ldc + n);
                cp[0] = v0; cp[1] = v1;
            }
            __syncwarp();
        }
    }
}

// ---------------- row softmax (fp32 in, fp16 out) ------------------------------
__global__ void __launch_bounds__(256) softmax_kernel(
    const float* __restrict__ S, __half* __restrict__ P)
{
    const long row = (long)blockIdx.y * gridDim.x + blockIdx.x;
    const float* p = S + row * NTOK;
    __half* q = P + row * NTOK;
    const int tid = threadIdx.x;

    float vals[16];
    float mx = -1e30f;
#pragma unroll
    for (int i = 0; i < 4; i++) {
        float4 v4 = ((const float4*)p)[tid + i * 256];
        vals[i*4+0] = v4.x; vals[i*4+1] = v4.y;
        vals[i*4+2] = v4.z; vals[i*4+3] = v4.w;
        mx = fmaxf(fmaxf(fmaxf(mx, v4.x), fmaxf(v4.y, v4.z)), v4.w);
    }

    __shared__ float sm[32];
#pragma unroll
    for (int o = 16; o > 0; o >>= 1) mx = fmaxf(mx, __shfl_xor_sync(0xffffffffu, mx, o));
    if ((tid & 31) == 0) sm[tid >> 5] = mx;
    __syncthreads();
    if (tid < 32) {
        float v = (tid < 8) ? sm[tid] : -1e30f;
#pragma unroll
        for (int o = 4; o > 0; o >>= 1) v = fmaxf(v, __shfl_xor_sync(0xffffffffu, v, o));
        if (tid == 0) sm[0] = v;
    }
    __syncthreads();
    mx = sm[0];
    __syncthreads();

    float sum = 0.f;
#pragma unroll
    for (int i = 0; i < 16; i++) {
        vals[i] = expf(vals[i] - mx);
        sum += vals[i];
    }
#pragma unroll
    for (int o = 16; o > 0; o >>= 1) sum += __shfl_xor_sync(0xffffffffu, sum, o);
    if ((tid & 31) == 0) sm[tid >> 5] = sum;
    __syncthreads();
    if (tid < 32) {
        float v = (tid < 8) ? sm[tid] : 0.f;
#pragma unroll
        for (int o = 4; o > 0; o >>= 1) v += __shfl_xor_sync(0xffffffffu, v, o);
        if (tid == 0) sm[0] = v;
    }
    __syncthreads();
    const float inv = 1.f / sm[0];
#pragma unroll
    for (int i = 0; i < 4; i++) {
        __half2 h0 = __floats2half2_rn(vals[i*4+0] * inv, vals[i*4+1] * inv);
        __half2 h1 = __floats2half2_rn(vals[i*4+2] * inv, vals[i*4+3] * inv);
        uint2 o; o.x = *(unsigned*)&h0; o.y = *(unsigned*)&h1;
        ((uint2*)q)[tid + i * 256] = o;
    }
}

// ---------------- launcher ----------------------------------------------------
extern "C" void kernel_launch(void* const* d_in, const int* in_sizes, int n_in,
                              void* d_out, int out_size)
{
    const float* x    = (const float*)d_in[0];
    const float* gn_w = (const float*)d_in[1];
    const float* gn_b = (const float*)d_in[2];
    const float* wq   = (const float*)d_in[3];
    const float* bq   = (const float*)d_in[4];
    const float* wk   = (const float*)d_in[5];
    const float* bk   = (const float*)d_in[6];
    const float* wv   = (const float*)d_in[7];
    const float* bv   = (const float*)d_in[8];
    const float* wp   = (const float*)d_in[9];
    const float* bp   = (const float*)d_in[10];
    float* out = (float*)d_out;

    __half *hn, *q, *k, *v, *o, *p, *wh;
    float *s;
    cudaGetSymbolAddress((void**)&hn, g_hn);
    cudaGetSymbolAddress((void**)&q,  g_q);
    cudaGetSymbolAddress((void**)&k,  g_k);
    cudaGetSymbolAddress((void**)&v,  g_v);
    cudaGetSymbolAddress((void**)&o,  g_o);
    cudaGetSymbolAddress((void**)&s,  g_s);
    cudaGetSymbolAddress((void**)&p,  g_p);
    cudaGetSymbolAddress((void**)&wh, g_wh);

    // 0. weights -> fp16
    convert_w_kernel<<<256, 256>>>(wq, wk, wv, wp, wh);

    // 1. GroupNorm -> fp16 hn
    groupnorm_kernel<<<dim3(GROUPS, BATCH), 256>>>(x, gn_w, gn_b, hn);

    const __half* whq = wh;
    const __half* whk = wh + (long)C * C;
    const __half* whv = wh + 2L * C * C;
    const __half* whp = wh + 3L * C * C;

    // 2. Q/K/V projections (fp16 out)
    {
        dim3 grid(NTOK / BN, C / BM, BATCH);
        h_gemm_kernel<false, false, __half><<<grid, 256>>>(whq, hn, q, C, C, NTOK, NTOK,
                                                           0, CN, CN, bq, 1.f, nullptr, 0);
        h_gemm_kernel<false, false, __half><<<grid, 256>>>(whk, hn, k, C, C, NTOK, NTOK,
                                                           0, CN, CN, bk, 1.f, nullptr, 0);
        h_gemm_kernel<false, false, __half><<<grid, 256>>>(whv, hn, v, C, C, NTOK, NTOK,
                                                           0, CN, CN, bv, 1.f, nullptr, 0);
    }

    // 3. scores = scale * q^T k  (fp32 out)
    {
        dim3 grid(NTOK / BN, NTOK / BM, BATCH);
        const float scale = 0.044194173824159216f; // 512^-0.5
        h_gemm_kernel<true, false, float><<<grid, 256>>>(q, k, s, C, NTOK, NTOK, NTOK,
                                                         CN, CN, NN, nullptr, scale,
                                                         nullptr, 0);
    }

    // 4. softmax -> fp16 probs
    softmax_kernel<<<dim3(NTOK, BATCH), 256>>>(s, p);

    // 5. o = v @ attn^T (fp16 out)
    {
        dim3 grid(NTOK / BN, C / BM, BATCH);
        h_gemm_kernel<false, true, __half><<<grid, 256>>>(v, p, o, NTOK, NTOK, NTOK, NTOK,
                                                          CN, NN, CN, nullptr, 1.f,
                                                          nullptr, 0);
    }

    // 6. out = x + wp @ o + bp  (fp32 out, residual)
    {
        dim3 grid(NTOK / BN, C / BM, BATCH);
        h_gemm_kernel<false, false, float><<<grid, 256>>>(whp, o, out, C, C, NTOK, NTOK,
                                                          0, CN, CN, bp, 1.f, x, CN);
    }
}

// round 11
// speedup vs baseline: 8.1408x; 1.0543x over previous
#include <cuda_runtime.h>
#include <cuda_fp16.h>
#include <mma.h>
#include <math.h>

using namespace nvcuda;

// Problem constants
#define BATCH 2
#define C 512
#define NTOK 4096
#define GROUPS 32
#define CPG 16
#define CN (C * NTOK)
#define NN ((long)NTOK * NTOK)

// ---------------- scratch (device globals) ------------------------------------
__device__ __half g_hn [(long)BATCH * CN];
__device__ __half g_qkv[(long)BATCH * 3 * CN];  // q;k;v per batch [1536][4096]
__device__ __half g_o  [(long)BATCH * CN];
__device__ float  g_s  [(long)BATCH * NN];      // fp32 scores (134 MB)
__device__ __half g_p  [(long)BATCH * NN];      // fp16 probs  (67 MB)
__device__ __half g_wh [4L * C * C];            // fp16 weights (wq;wk;wv;wp)
__device__ float  g_b3 [3 * C];                 // packed qkv bias

// ---------------- weight/bias conversion ---------------------------------------
__global__ void __launch_bounds__(256) convert_w_kernel(
    const float* __restrict__ wq, const float* __restrict__ wk,
    const float* __restrict__ wv, const float* __restrict__ wp,
    const float* __restrict__ bq, const float* __restrict__ bk,
    const float* __restrict__ bv, __half* __restrict__ wh,
    float* __restrict__ b3)
{
    const int n = C * C;
    for (int i = blockIdx.x * 256 + threadIdx.x; i < n; i += gridDim.x * 256) {
        wh[i]         = __float2half_rn(wq[i]);
        wh[i + n]     = __float2half_rn(wk[i]);
        wh[i + 2 * n] = __float2half_rn(wv[i]);
        wh[i + 3 * n] = __float2half_rn(wp[i]);
    }
    int t = blockIdx.x * 256 + threadIdx.x;
    if (t < C) { b3[t] = bq[t]; b3[t + C] = bk[t]; b3[t + 2 * C] = bv[t]; }
}

// ---------------- GroupNorm (fp32 in, fp16 out) --------------------------------
__global__ void __launch_bounds__(256) groupnorm_kernel(
    const float* __restrict__ x, const float* __restrict__ w,
    const float* __restrict__ b, __half* __restrict__ hn)
{
    const int g  = blockIdx.x;
    const int bb = blockIdx.y;
    const long base = ((long)bb * C + (long)g * CPG) * NTOK;
    const int total = CPG * NTOK;

    float s = 0.f, s2 = 0.f;
    for (int i = threadIdx.x; i < total / 4; i += 256) {
        float4 v = ((const float4*)(x + base))[i];
        s  += v.x + v.y + v.z + v.w;
        s2 += v.x*v.x + v.y*v.y + v.z*v.z + v.w*v.w;
    }
    __shared__ float rs[256], rs2[256];
    rs[threadIdx.x] = s; rs2[threadIdx.x] = s2;
    __syncthreads();
    for (int off = 128; off > 0; off >>= 1) {
        if (threadIdx.x < off) {
            rs[threadIdx.x]  += rs[threadIdx.x + off];
            rs2[threadIdx.x] += rs2[threadIdx.x + off];
        }
        __syncthreads();
    }
    const float mean = rs[0] / (float)total;
    const float var  = rs2[0] / (float)total - mean * mean;
    const float rstd = rsqrtf(var + 1e-6f);

    for (int i = threadIdx.x; i < total / 4; i += 256) {
        float4 v = ((const float4*)(x + base))[i];
        int c = g * CPG + (i * 4) / NTOK;
        float sc = rstd * w[c], sh = b[c] - mean * sc;
        __half2 h0 = __floats2half2_rn(v.x * sc + sh, v.y * sc + sh);
        __half2 h1 = __floats2half2_rn(v.z * sc + sh, v.w * sc + sh);
        uint2 o; o.x = *(unsigned*)&h0; o.y = *(unsigned*)&h1;
        ((uint2*)(hn + base))[i] = o;
    }
}

// ---------------- fp16 tensor-core batched GEMM (3-stage pipeline) -------------
// C[m,n] = scale * sum_k A(m,k)*B(k,n) + bias[m] + R[m,n]
// AT: A stored A[k*lda+m]; BT: B stored B[n*ldb+k]. K%32==0, M,N%128==0.
#define BM 128
#define BN 128
#define BKH 32
#define STAGES 3
#define STG_H 5120                         // halfs per operand stage
#define SMEM_GEMM (STAGES * 2 * STG_H * 2) // 61440 bytes

__device__ __forceinline__ void cp16(void* s, const void* g) {
    unsigned sa = (unsigned)__cvta_generic_to_shared(s);
    asm volatile("cp.async.cg.shared.global [%0], [%1], 16;\n" :: "r"(sa), "l"(g));
}
#define CP_COMMIT() asm volatile("cp.async.commit_group;\n" ::: "memory")
#define CP_WAIT(n)  asm volatile("cp.async.wait_group %0;\n" :: "n"(n) : "memory")

template <bool AT, bool BT, typename OutT>
__global__ void __launch_bounds__(256) h_gemm_kernel(
    const __half* __restrict__ A, const __half* __restrict__ B,
    OutT* __restrict__ Cmat, int K, int lda, int ldb, int ldc,
    long sA, long sB, long sC,
    const float* __restrict__ bias, float scale,
    const float* __restrict__ R, long sR)
{
    extern __shared__ __align__(16) __half sh[];
    __half* As = sh;                        // STAGES stages of STG_H halfs
    __half* Bs = sh + STAGES * STG_H;

    const int bz = blockIdx.z;
    A += (long)bz * sA;
    B += (long)bz * sB;
    Cmat += (long)bz * sC;
    if (R) R += (long)bz * sR;

    const int m0 = blockIdx.y * BM;
    const int n0 = blockIdx.x * BN;

    const int tid  = threadIdx.x;
    const int warp = tid >> 5;
    const int lane = tid & 31;
    const int wm = warp & 1;      // 2 warps in m (64 rows each)
    const int wn = warp >> 1;     // 4 warps in n (32 cols each)

    wmma::fragment<wmma::accumulator, 16, 16, 16, float> cf[4][2];
#pragma unroll
    for (int i = 0; i < 4; i++)
#pragma unroll
        for (int j = 0; j < 2; j++) wmma::fill_fragment(cf[i][j], 0.f);

    auto loadA = [&](int st, int kt) {
        const int k0 = kt * BKH;
        __half* dst = As + st * STG_H;
#pragma unroll
        for (int r = 0; r < 2; r++) {
            int t = tid + r * 256;
            if (AT) {           // A[k*lda + m], contiguous in m
                int k = t >> 4, ch = t & 15;
                cp16(dst + k * 136 + ch * 8, A + (long)(k0 + k) * lda + m0 + ch * 8);
            } else {            // A[m*lda + k], contiguous in k
                int m = t >> 2, ch = t & 3;
                cp16(dst + m * 40 + ch * 8, A + (long)(m0 + m) * lda + k0 + ch * 8);
            }
        }
    };
    auto loadB = [&](int st, int kt) {
        const int k0 = kt * BKH;
        __half* dst = Bs + st * STG_H;
#pragma unroll
        for (int r = 0; r < 2; r++) {
            int t = tid + r * 256;
            if (BT) {           // B[n*ldb + k], contiguous in k
                int n = t >> 2, ch = t & 3;
                cp16(dst + n * 40 + ch * 8, B + (long)(n0 + n) * ldb + k0 + ch * 8);
            } else {            // B[k*ldb + n], contiguous in n
                int k = t >> 4, ch = t & 15;
                cp16(dst + k * 136 + ch * 8, B + (long)(k0 + k) * ldb + n0 + ch * 8);
            }
        }
    };

    const int KT = K / BKH;
    // prologue: stages 0..STAGES-2
#pragma unroll
    for (int i = 0; i < STAGES - 1; i++) {
        loadA(i, i); loadB(i, i);
        CP_COMMIT();
    }

    int st = 0;
    for (int kt = 0; kt < KT; kt++) {
        CP_WAIT(STAGES - 2);
        __syncthreads();

        const __half* as = As + st * STG_H;
        const __half* bs = Bs + st * STG_H;
#pragma unroll
        for (int kk = 0; kk < BKH; kk += 16) {
            typedef typename wmma::fragment<wmma::matrix_a, 16, 16, 16, __half,
                typename std::conditional<AT, wmma::col_major, wmma::row_major>::type> AFrag;
            typedef typename wmma::fragment<wmma::matrix_b, 16, 16, 16, __half,
                typename std::conditional<BT, wmma::col_major, wmma::row_major>::type> BFrag;
            AFrag af[4];
            BFrag bf[2];
#pragma unroll
            for (int i = 0; i < 4; i++) {
                if (AT)
                    wmma::load_matrix_sync(af[i], &as[kk * 136 + wm * 64 + i * 16], 136);
                else
                    wmma::load_matrix_sync(af[i], &as[(wm * 64 + i * 16) * 40 + kk], 40);
            }
#pragma unroll
            for (int j = 0; j < 2; j++) {
                if (BT)
                    wmma::load_matrix_sync(bf[j], &bs[(wn * 32 + j * 16) * 40 + kk], 40);
                else
                    wmma::load_matrix_sync(bf[j], &bs[kk * 136 + wn * 32 + j * 16], 136);
            }
#pragma unroll
            for (int i = 0; i < 4; i++)
#pragma unroll
                for (int j = 0; j < 2; j++)
                    wmma::mma_sync(cf[i][j], af[i], bf[j], cf[i][j]);
        }

        const int nk = kt + STAGES - 1;
        if (nk < KT) {
            const int nst = (st + STAGES - 1) % STAGES;
            loadA(nst, nk); loadB(nst, nk);
        }
        CP_COMMIT();
        st = (st + 1) % STAGES;
    }

    __syncthreads();   // before reusing smem for staging

    // ---- epilogue: scale, +bias[m], +R[m,n], convert ----
    float* stage = reinterpret_cast<float*>(sh) + warp * 256;
    const int r  = lane >> 1;        // 0..15 row within frag
    const int ch = lane & 1;         // 0/1: which 8-col chunk

#pragma unroll
    for (int i = 0; i < 4; i++) {
#pragma unroll
        for (int j = 0; j < 2; j++) {
            wmma::store_matrix_sync(stage, cf[i][j], 16, wmma::mem_row_major);
            __syncwarp();
            const int m = m0 + wm * 64 + i * 16 + r;
            const int n = n0 + wn * 32 + j * 16 + ch * 8;
            float4 v0 = ((float4*)stage)[r * 4 + ch * 2];
            float4 v1 = ((float4*)stage)[r * 4 + ch * 2 + 1];
            float bv = bias ? bias[m] : 0.f;
            v0.x = v0.x * scale + bv; v0.y = v0.y * scale + bv;
            v0.z = v0.z * scale + bv; v0.w = v0.w * scale + bv;
            v1.x = v1.x * scale + bv; v1.y = v1.y * scale + bv;
            v1.z = v1.z * scale + bv; v1.w = v1.w * scale + bv;
            if (R) {
                const float4* rp = (const float4*)(R + (long)m * ldc + n);
                float4 r0 = rp[0], r1 = rp[1];
                v0.x += r0.x; v0.y += r0.y; v0.z += r0.z; v0.w += r0.w;
                v1.x += r1.x; v1.y += r1.y; v1.z += r1.z; v1.w += r1.w;
            }
            if (sizeof(OutT) == 2) {
                __half2 h0 = __floats2half2_rn(v0.x, v0.y);
                __half2 h1 = __floats2half2_rn(v0.z, v0.w);
                __half2 h2 = __floats2half2_rn(v1.x, v1.y);
                __half2 h3 = __floats2half2_rn(v1.z, v1.w);
                uint4 o;
                o.x = *(unsigned*)&h0; o.y = *(unsigned*)&h1;
                o.z = *(unsigned*)&h2; o.w = *(unsigned*)&h3;
                *((uint4*)((__half*)Cmat + (long)m * ldc + n)) = o;
            } else {
                float4* cp = (float4*)((float*)Cmat + (long)m * ldc + n);
                cp[0] = v0; cp[1] = v1;
            }
            __syncwarp();
        }
    }
}

// ---------------- row softmax (fp32 in, fp16 out) ------------------------------
__global__ void __launch_bounds__(256) softmax_kernel(
    const float* __restrict__ S, __half* __restrict__ P)
{
    const long row = (long)blockIdx.y * gridDim.x + blockIdx.x;
    const float* p = S + row * NTOK;
    __half* q = P + row * NTOK;
    const int tid = threadIdx.x;

    float vals[16];
    float mx = -1e30f;
#pragma unroll
    for (int i = 0; i < 4; i++) {
        float4 v4 = ((const float4*)p)[tid + i * 256];
        vals[i*4+0] = v4.x; vals[i*4+1] = v4.y;
        vals[i*4+2] = v4.z; vals[i*4+3] = v4.w;
        mx = fmaxf(fmaxf(fmaxf(mx, v4.x), fmaxf(v4.y, v4.z)), v4.w);
    }

    __shared__ float sm[32];
#pragma unroll
    for (int o = 16; o > 0; o >>= 1) mx = fmaxf(mx, __shfl_xor_sync(0xffffffffu, mx, o));
    if ((tid & 31) == 0) sm[tid >> 5] = mx;
    __syncthreads();
    if (tid < 32) {
        float v = (tid < 8) ? sm[tid] : -1e30f;
#pragma unroll
        for (int o = 4; o > 0; o >>= 1) v = fmaxf(v, __shfl_xor_sync(0xffffffffu, v, o));
        if (tid == 0) sm[0] = v;
    }
    __syncthreads();
    mx = sm[0];
    __syncthreads();

    float sum = 0.f;
#pragma unroll
    for (int i = 0; i < 16; i++) {
        vals[i] = expf(vals[i] - mx);
        sum += vals[i];
    }
#pragma unroll
    for (int o = 16; o > 0; o >>= 1) sum += __shfl_xor_sync(0xffffffffu, sum, o);
    if ((tid & 31) == 0) sm[tid >> 5] = sum;
    __syncthreads();
    if (tid < 32) {
        float v = (tid < 8) ? sm[tid] : 0.f;
#pragma unroll
        for (int o = 4; o > 0; o >>= 1) v += __shfl_xor_sync(0xffffffffu, v, o);
        if (tid == 0) sm[0] = v;
    }
    __syncthreads();
    const float inv = 1.f / sm[0];
#pragma unroll
    for (int i = 0; i < 4; i++) {
        __half2 h0 = __floats2half2_rn(vals[i*4+0] * inv, vals[i*4+1] * inv);
        __half2 h1 = __floats2half2_rn(vals[i*4+2] * inv, vals[i*4+3] * inv);
        uint2 o; o.x = *(unsigned*)&h0; o.y = *(unsigned*)&h1;
        ((uint2*)q)[tid + i * 256] = o;
    }
}

// ---------------- launcher ----------------------------------------------------
extern "C" void kernel_launch(void* const* d_in, const int* in_sizes, int n_in,
                              void* d_out, int out_size)
{
    const float* x    = (const float*)d_in[0];
    const float* gn_w = (const float*)d_in[1];
    const float* gn_b = (const float*)d_in[2];
    const float* wq   = (const float*)d_in[3];
    const float* bq   = (const float*)d_in[4];
    const float* wk   = (const float*)d_in[5];
    const float* bk   = (const float*)d_in[6];
    const float* wv   = (const float*)d_in[7];
    const float* bv   = (const float*)d_in[8];
    const float* wp   = (const float*)d_in[9];
    const float* bp   = (const float*)d_in[10];
    float* out = (float*)d_out;

    __half *hn, *qkv, *o, *p, *wh;
    float *s, *b3;
    cudaGetSymbolAddress((void**)&hn,  g_hn);
    cudaGetSymbolAddress((void**)&qkv, g_qkv);
    cudaGetSymbolAddress((void**)&o,   g_o);
    cudaGetSymbolAddress((void**)&s,   g_s);
    cudaGetSymbolAddress((void**)&p,   g_p);
    cudaGetSymbolAddress((void**)&wh,  g_wh);
    cudaGetSymbolAddress((void**)&b3,  g_b3);

    cudaFuncSetAttribute((const void*)h_gemm_kernel<false, false, __half>,
        cudaFuncAttributeMaxDynamicSharedMemorySize, SMEM_GEMM);
    cudaFuncSetAttribute((const void*)h_gemm_kernel<true, false, float>,
        cudaFuncAttributeMaxDynamicSharedMemorySize, SMEM_GEMM);
    cudaFuncSetAttribute((const void*)h_gemm_kernel<false, true, __half>,
        cudaFuncAttributeMaxDynamicSharedMemorySize, SMEM_GEMM);
    cudaFuncSetAttribute((const void*)h_gemm_kernel<false, false, float>,
        cudaFuncAttributeMaxDynamicSharedMemorySize, SMEM_GEMM);

    // 0. weights/bias -> fp16 / packed
    convert_w_kernel<<<256, 256>>>(wq, wk, wv, wp, bq, bk, bv, wh, b3);

    // 1. GroupNorm -> fp16 hn [c][n]
    groupnorm_kernel<<<dim3(GROUPS, BATCH), 256>>>(x, gn_w, gn_b, hn);

    // 2. fused QKV: qkv[o][n] = W3[o][c] * hn[c][n] + b3[o]  (M=1536, fp16 out)
    {
        dim3 grid(NTOK / BN, 3 * C / BM, BATCH);
        h_gemm_kernel<false, false, __half><<<grid, 256, SMEM_GEMM>>>(
            wh, hn, qkv, C, C, NTOK, NTOK, 0, CN, 3L * CN, b3, 1.f, nullptr, 0);
    }

    const long qofs = 0, kofs = CN, vofs = 2L * CN;

    // 3. scores[i][j] = scale * sum_c q[c][i] k[c][j]  (AT, fp32 out)
    {
        dim3 grid(NTOK / BN, NTOK / BM, BATCH);
        h_gemm_kernel<true, false, float><<<grid, 256, SMEM_GEMM>>>(
            qkv + qofs, qkv + kofs, s, C, NTOK, NTOK, NTOK,
            3L * CN, 3L * CN, NN, nullptr, 0.044194173824159216f, nullptr, 0);
    }

    // 4. softmax -> fp16 probs [i][j]
    softmax_kernel<<<dim3(NTOK, BATCH), 256>>>(s, p);

    // 5. o[c][i] = sum_j v[c][j] p[i][j]  (BT, fp16 out)
    {
        dim3 grid(NTOK / BN, C / BM, BATCH);
        h_gemm_kernel<false, true, __half><<<grid, 256, SMEM_GEMM>>>(
            qkv + vofs, p, o, NTOK, NTOK, NTOK, NTOK,
            3L * CN, NN, CN, nullptr, 1.f, nullptr, 0);
    }

    // 6. out = x + wp @ o + bp  (fp32 out, residual)
    {
        dim3 grid(NTOK / BN, C / BM, BATCH);
        h_gemm_kernel<false, false, float><<<grid, 256, SMEM_GEMM>>>(
            wh + 3L * C * C, o, out, C, C, NTOK, NTOK,
            0, CN, CN, bp, 1.f, x, CN);
    }
}

// round 13
// speedup vs baseline: 8.3701x; 1.0282x over previous
#include <cuda_runtime.h>
#include <cuda_fp16.h>
#include <mma.h>
#include <math.h>

using namespace nvcuda;

// Problem constants
#define BATCH 2
#define C 512
#define NTOK 4096
#define GROUPS 32
#define CPG 16
#define CN (C * NTOK)
#define NN ((long)NTOK * NTOK)

// ---------------- scratch (device globals) ------------------------------------
__device__ __half g_hn [(long)BATCH * CN];
__device__ __half g_qkv[(long)BATCH * 3 * CN];  // q;k;v per batch [1536][4096]
__device__ __half g_o  [(long)BATCH * CN];
__device__ float  g_s  [(long)BATCH * NN];      // fp32 scores (134 MB)
__device__ __half g_p  [(long)BATCH * NN];      // fp16 probs  (67 MB)
__device__ __half g_wh [4L * C * C];            // fp16 weights (wq;wk;wv;wp)
__device__ float  g_b3 [3 * C];                 // packed qkv bias

// ---------------- weight/bias conversion ---------------------------------------
__global__ void __launch_bounds__(256) convert_w_kernel(
    const float* __restrict__ wq, const float* __restrict__ wk,
    const float* __restrict__ wv, const float* __restrict__ wp,
    const float* __restrict__ bq, const float* __restrict__ bk,
    const float* __restrict__ bv, __half* __restrict__ wh,
    float* __restrict__ b3)
{
    const int n = C * C;
    for (int i = blockIdx.x * 256 + threadIdx.x; i < n; i += gridDim.x * 256) {
        wh[i]         = __float2half_rn(wq[i]);
        wh[i + n]     = __float2half_rn(wk[i]);
        wh[i + 2 * n] = __float2half_rn(wv[i]);
        wh[i + 3 * n] = __float2half_rn(wp[i]);
    }
    int t = blockIdx.x * 256 + threadIdx.x;
    if (t < C) { b3[t] = bq[t]; b3[t + C] = bk[t]; b3[t + 2 * C] = bv[t]; }
}

// ---------------- GroupNorm (fp32 in, fp16 out) --------------------------------
__global__ void __launch_bounds__(256) groupnorm_kernel(
    const float* __restrict__ x, const float* __restrict__ w,
    const float* __restrict__ b, __half* __restrict__ hn)
{
    const int g  = blockIdx.x;
    const int bb = blockIdx.y;
    const long base = ((long)bb * C + (long)g * CPG) * NTOK;
    const int total = CPG * NTOK;

    float s = 0.f, s2 = 0.f;
    for (int i = threadIdx.x; i < total / 4; i += 256) {
        float4 v = ((const float4*)(x + base))[i];
        s  += v.x + v.y + v.z + v.w;
        s2 += v.x*v.x + v.y*v.y + v.z*v.z + v.w*v.w;
    }
    __shared__ float rs[256], rs2[256];
    rs[threadIdx.x] = s; rs2[threadIdx.x] = s2;
    __syncthreads();
    for (int off = 128; off > 0; off >>= 1) {
        if (threadIdx.x < off) {
            rs[threadIdx.x]  += rs[threadIdx.x + off];
            rs2[threadIdx.x] += rs2[threadIdx.x + off];
        }
        __syncthreads();
    }
    const float mean = rs[0] / (float)total;
    const float var  = rs2[0] / (float)total - mean * mean;
    const float rstd = rsqrtf(var + 1e-6f);

    for (int i = threadIdx.x; i < total / 4; i += 256) {
        float4 v = ((const float4*)(x + base))[i];
        int c = g * CPG + (i * 4) / NTOK;
        float sc = rstd * w[c], sh = b[c] - mean * sc;
        __half2 h0 = __floats2half2_rn(v.x * sc + sh, v.y * sc + sh);
        __half2 h1 = __floats2half2_rn(v.z * sc + sh, v.w * sc + sh);
        uint2 o; o.x = *(unsigned*)&h0; o.y = *(unsigned*)&h1;
        ((uint2*)(hn + base))[i] = o;
    }
}

// ---------------- fp16 tensor-core batched GEMM --------------------------------
// 128x128x32 block tile, 128 threads (4 warps 2x2), 64x64 warp tile (4x4 frags),
// 3-stage cp.async pipeline.
// C[m,n] = scale * sum_k A(m,k)*B(k,n) + bias[m] + R[m,n]
// AT: A stored A[k*lda+m]; BT: B stored B[n*ldb+k]. K%32==0, M,N%128==0.
#define BM 128
#define BN 128
#define BKH 32
#define STAGES 3
#define STG_H 5120                         // halfs per operand stage
#define SMEM_GEMM (STAGES * 2 * STG_H * 2) // 61440 bytes
#define GTHREADS 128

__device__ __forceinline__ void cp16(void* s, const void* g) {
    unsigned sa = (unsigned)__cvta_generic_to_shared(s);
    asm volatile("cp.async.cg.shared.global [%0], [%1], 16;\n" :: "r"(sa), "l"(g));
}
#define CP_COMMIT() asm volatile("cp.async.commit_group;\n" ::: "memory")
#define CP_WAIT(n)  asm volatile("cp.async.wait_group %0;\n" :: "n"(n) : "memory")

template <bool AT, bool BT, typename OutT>
__global__ void __launch_bounds__(GTHREADS) h_gemm_kernel(
    const __half* __restrict__ A, const __half* __restrict__ B,
    OutT* __restrict__ Cmat, int K, int lda, int ldb, int ldc,
    long sA, long sB, long sC,
    const float* __restrict__ bias, float scale,
    const float* __restrict__ R, long sR)
{
    extern __shared__ __align__(16) __half sh[];
    __half* As = sh;                        // STAGES stages of STG_H halfs
    __half* Bs = sh + STAGES * STG_H;

    const int bz = blockIdx.z;
    A += (long)bz * sA;
    B += (long)bz * sB;
    Cmat += (long)bz * sC;
    if (R) R += (long)bz * sR;

    const int m0 = blockIdx.y * BM;
    const int n0 = blockIdx.x * BN;

    const int tid  = threadIdx.x;
    const int warp = tid >> 5;
    const int lane = tid & 31;
    const int wm = warp & 1;      // 2 warps in m (64 rows each)
    const int wn = warp >> 1;     // 2 warps in n (64 cols each)

    wmma::fragment<wmma::accumulator, 16, 16, 16, float> cf[4][4];
#pragma unroll
    for (int i = 0; i < 4; i++)
#pragma unroll
        for (int j = 0; j < 4; j++) wmma::fill_fragment(cf[i][j], 0.f);

    auto loadA = [&](int st, int kt) {
        const int k0 = kt * BKH;
        __half* dst = As + st * STG_H;
#pragma unroll
        for (int r = 0; r < 4; r++) {      // 512 chunks of 16B / 128 threads
            int t = tid + r * GTHREADS;
            if (AT) {           // A[k*lda + m], contiguous in m  -> [32][136]
                int k = t >> 4, ch = t & 15;
                cp16(dst + k * 136 + ch * 8, A + (long)(k0 + k) * lda + m0 + ch * 8);
            } else {            // A[m*lda + k], contiguous in k  -> [128][40]
                int m = t >> 2, ch = t & 3;
                cp16(dst + m * 40 + ch * 8, A + (long)(m0 + m) * lda + k0 + ch * 8);
            }
        }
    };
    auto loadB = [&](int st, int kt) {
        const int k0 = kt * BKH;
        __half* dst = Bs + st * STG_H;
#pragma unroll
        for (int r = 0; r < 4; r++) {
            int t = tid + r * GTHREADS;
            if (BT) {           // B[n*ldb + k], contiguous in k  -> [128][40]
                int n = t >> 2, ch = t & 3;
                cp16(dst + n * 40 + ch * 8, B + (long)(n0 + n) * ldb + k0 + ch * 8);
            } else {            // B[k*ldb + n], contiguous in n  -> [32][136]
                int k = t >> 4, ch = t & 15;
                cp16(dst + k * 136 + ch * 8, B + (long)(k0 + k) * ldb + n0 + ch * 8);
            }
        }
    };

    const int KT = K / BKH;
    // prologue: stages 0..STAGES-2
#pragma unroll
    for (int i = 0; i < STAGES - 1; i++) {
        loadA(i, i); loadB(i, i);
        CP_COMMIT();
    }

    int st = 0;
    for (int kt = 0; kt < KT; kt++) {
        CP_WAIT(STAGES - 2);
        __syncthreads();

        const __half* as = As + st * STG_H;
        const __half* bs = Bs + st * STG_H;
#pragma unroll
        for (int kk = 0; kk < BKH; kk += 16) {
            typedef typename wmma::fragment<wmma::matrix_a, 16, 16, 16, __half,
                typename std::conditional<AT, wmma::col_major, wmma::row_major>::type> AFrag;
            typedef typename wmma::fragment<wmma::matrix_b, 16, 16, 16, __half,
                typename std::conditional<BT, wmma::col_major, wmma::row_major>::type> BFrag;
            AFrag af[4];
            BFrag bf[4];
#pragma unroll
            for (int i = 0; i < 4; i++) {
                if (AT)
                    wmma::load_matrix_sync(af[i], &as[kk * 136 + wm * 64 + i * 16], 136);
                else
                    wmma::load_matrix_sync(af[i], &as[(wm * 64 + i * 16) * 40 + kk], 40);
            }
#pragma unroll
            for (int j = 0; j < 4; j++) {
                if (BT)
                    wmma::load_matrix_sync(bf[j], &bs[(wn * 64 + j * 16) * 40 + kk], 40);
                else
                    wmma::load_matrix_sync(bf[j], &bs[kk * 136 + wn * 64 + j * 16], 136);
            }
#pragma unroll
            for (int i = 0; i < 4; i++)
#pragma unroll
                for (int j = 0; j < 4; j++)
                    wmma::mma_sync(cf[i][j], af[i], bf[j], cf[i][j]);
        }

        const int nk = kt + STAGES - 1;
        if (nk < KT) {
            const int nst = (st + STAGES - 1) % STAGES;
            loadA(nst, nk); loadB(nst, nk);
        }
        CP_COMMIT();
        st = (st + 1) % STAGES;
    }

    __syncthreads();   // before reusing smem for staging

    // ---- epilogue: scale, +bias[m], +R[m,n], convert ----
    float* stage = reinterpret_cast<float*>(sh) + warp * 256;
    const int r  = lane >> 1;        // 0..15 row within frag
    const int ch = lane & 1;         // 0/1: which 8-col chunk

#pragma unroll
    for (int i = 0; i < 4; i++) {
#pragma unroll
        for (int j = 0; j < 4; j++) {
            wmma::store_matrix_sync(stage, cf[i][j], 16, wmma::mem_row_major);
            __syncwarp();
            const int m = m0 + wm * 64 + i * 16 + r;
            const int n = n0 + wn * 64 + j * 16 + ch * 8;
            float4 v0 = ((float4*)stage)[r * 4 + ch * 2];
            float4 v1 = ((float4*)stage)[r * 4 + ch * 2 + 1];
            float bv = bias ? bias[m] : 0.f;
            v0.x = v0.x * scale + bv; v0.y = v0.y * scale + bv;
            v0.z = v0.z * scale + bv; v0.w = v0.w * scale + bv;
            v1.x = v1.x * scale + bv; v1.y = v1.y * scale + bv;
            v1.z = v1.z * scale + bv; v1.w = v1.w * scale + bv;
            if (R) {
                const float4* rp = (const float4*)(R + (long)m * ldc + n);
                float4 r0 = rp[0], r1 = rp[1];
                v0.x += r0.x; v0.y += r0.y; v0.z += r0.z; v0.w += r0.w;
                v1.x += r1.x; v1.y += r1.y; v1.z += r1.z; v1.w += r1.w;
            }
            if (sizeof(OutT) == 2) {
                __half2 h0 = __floats2half2_rn(v0.x, v0.y);
                __half2 h1 = __floats2half2_rn(v0.z, v0.w);
                __half2 h2 = __floats2half2_rn(v1.x, v1.y);
                __half2 h3 = __floats2half2_rn(v1.z, v1.w);
                uint4 o;
                o.x = *(unsigned*)&h0; o.y = *(unsigned*)&h1;
                o.z = *(unsigned*)&h2; o.w = *(unsigned*)&h3;
                *((uint4*)((__half*)Cmat + (long)m * ldc + n)) = o;
            } else {
                float4* cp = (float4*)((float*)Cmat + (long)m * ldc + n);
                cp[0] = v0; cp[1] = v1;
            }
            __syncwarp();
        }
    }
}

// ---------------- row softmax (fp32 in, fp16 out) ------------------------------
__global__ void __launch_bounds__(256) softmax_kernel(
    const float* __restrict__ S, __half* __restrict__ P)
{
    const long row = (long)blockIdx.y * gridDim.x + blockIdx.x;
    const float* p = S + row * NTOK;
    __half* q = P + row * NTOK;
    const int tid = threadIdx.x;

    float vals[16];
    float mx = -1e30f;
#pragma unroll
    for (int i = 0; i < 4; i++) {
        float4 v4 = ((const float4*)p)[tid + i * 256];
        vals[i*4+0] = v4.x; vals[i*4+1] = v4.y;
        vals[i*4+2] = v4.z; vals[i*4+3] = v4.w;
        mx = fmaxf(fmaxf(fmaxf(mx, v4.x), fmaxf(v4.y, v4.z)), v4.w);
    }

    __shared__ float sm[32];
#pragma unroll
    for (int o = 16; o > 0; o >>= 1) mx = fmaxf(mx, __shfl_xor_sync(0xffffffffu, mx, o));
    if ((tid & 31) == 0) sm[tid >> 5] = mx;
    __syncthreads();
    if (tid < 32) {
        float v = (tid < 8) ? sm[tid] : -1e30f;
#pragma unroll
        for (int o = 4; o > 0; o >>= 1) v = fmaxf(v, __shfl_xor_sync(0xffffffffu, v, o));
        if (tid == 0) sm[0] = v;
    }
    __syncthreads();
    mx = sm[0];
    __syncthreads();

    float sum = 0.f;
#pragma unroll
    for (int i = 0; i < 16; i++) {
        vals[i] = expf(vals[i] - mx);
        sum += vals[i];
    }
#pragma unroll
    for (int o = 16; o > 0; o >>= 1) sum += __shfl_xor_sync(0xffffffffu, sum, o);
    if ((tid & 31) == 0) sm[tid >> 5] = sum;
    __syncthreads();
    if (tid < 32) {
        float v = (tid < 8) ? sm[tid] : 0.f;
#pragma unroll
        for (int o = 4; o > 0; o >>= 1) v += __shfl_xor_sync(0xffffffffu, v, o);
        if (tid == 0) sm[0] = v;
    }
    __syncthreads();
    const float inv = 1.f / sm[0];
#pragma unroll
    for (int i = 0; i < 4; i++) {
        __half2 h0 = __floats2half2_rn(vals[i*4+0] * inv, vals[i*4+1] * inv);
        __half2 h1 = __floats2half2_rn(vals[i*4+2] * inv, vals[i*4+3] * inv);
        uint2 o; o.x = *(unsigned*)&h0; o.y = *(unsigned*)&h1;
        ((uint2*)q)[tid + i * 256] = o;
    }
}

// ---------------- launcher ----------------------------------------------------
extern "C" void kernel_launch(void* const* d_in, const int* in_sizes, int n_in,
                              void* d_out, int out_size)
{
    const float* x    = (const float*)d_in[0];
    const float* gn_w = (const float*)d_in[1];
    const float* gn_b = (const float*)d_in[2];
    const float* wq   = (const float*)d_in[3];
    const float* bq   = (const float*)d_in[4];
    const float* wk   = (const float*)d_in[5];
    const float* bk   = (const float*)d_in[6];
    const float* wv   = (const float*)d_in[7];
    const float* bv   = (const float*)d_in[8];
    const float* wp   = (const float*)d_in[9];
    const float* bp   = (const float*)d_in[10];
    float* out = (float*)d_out;

    __half *hn, *qkv, *o, *p, *wh;
    float *s, *b3;
    cudaGetSymbolAddress((void**)&hn,  g_hn);
    cudaGetSymbolAddress((void**)&qkv, g_qkv);
    cudaGetSymbolAddress((void**)&o,   g_o);
    cudaGetSymbolAddress((void**)&s,   g_s);
    cudaGetSymbolAddress((void**)&p,   g_p);
    cudaGetSymbolAddress((void**)&wh,  g_wh);
    cudaGetSymbolAddress((void**)&b3,  g_b3);

    cudaFuncSetAttribute((const void*)h_gemm_kernel<false, false, __half>,
        cudaFuncAttributeMaxDynamicSharedMemorySize, SMEM_GEMM);
    cudaFuncSetAttribute((const void*)h_gemm_kernel<true, false, float>,
        cudaFuncAttributeMaxDynamicSharedMemorySize, SMEM_GEMM);
    cudaFuncSetAttribute((const void*)h_gemm_kernel<false, true, __half>,
        cudaFuncAttributeMaxDynamicSharedMemorySize, SMEM_GEMM);
    cudaFuncSetAttribute((const void*)h_gemm_kernel<false, false, float>,
        cudaFuncAttributeMaxDynamicSharedMemorySize, SMEM_GEMM);

    // 0. weights/bias -> fp16 / packed
    convert_w_kernel<<<256, 256>>>(wq, wk, wv, wp, bq, bk, bv, wh, b3);

    // 1. GroupNorm -> fp16 hn [c][n]
    groupnorm_kernel<<<dim3(GROUPS, BATCH), 256>>>(x, gn_w, gn_b, hn);

    // 2. fused QKV: qkv[o][n] = W3[o][c] * hn[c][n] + b3[o]  (M=1536, fp16 out)
    {
        dim3 grid(NTOK / BN, 3 * C / BM, BATCH);
        h_gemm_kernel<false, false, __half><<<grid, GTHREADS, SMEM_GEMM>>>(
            wh, hn, qkv, C, C, NTOK, NTOK, 0, CN, 3L * CN, b3, 1.f, nullptr, 0);
    }

    const long qofs = 0, kofs = CN, vofs = 2L * CN;

    // 3. scores[i][j] = scale * sum_c q[c][i] k[c][j]  (AT, fp32 out)
    {
        dim3 grid(NTOK / BN, NTOK / BM, BATCH);
        h_gemm_kernel<true, false, float><<<grid, GTHREADS, SMEM_GEMM>>>(
            qkv + qofs, qkv + kofs, s, C, NTOK, NTOK, NTOK,
            3L * CN, 3L * CN, NN, nullptr, 0.044194173824159216f, nullptr, 0);
    }

    // 4. softmax -> fp16 probs [i][j]
    softmax_kernel<<<dim3(NTOK, BATCH), 256>>>(s, p);

    // 5. o[c][i] = sum_j v[c][j] p[i][j]  (BT, fp16 out)
    {
        dim3 grid(NTOK / BN, C / BM, BATCH);
        h_gemm_kernel<false, true, __half><<<grid, GTHREADS, SMEM_GEMM>>>(
            qkv + vofs, p, o, NTOK, NTOK, NTOK, NTOK,
            3L * CN, NN, CN, nullptr, 1.f, nullptr, 0);
    }

    // 6. out = x + wp @ o + bp  (fp32 out, residual)
    {
        dim3 grid(NTOK / BN, C / BM, BATCH);
        h_gemm_kernel<false, false, float><<<grid, GTHREADS, SMEM_GEMM>>>(
            wh + 3L * C * C, o, out, C, C, NTOK, NTOK,
            0, CN, CN, bp, 1.f, x, CN);
    }
}